// round 10
// baseline (speedup 1.0000x reference)
#include <cuda_runtime.h>
#include <math.h>

#define N_PTS 12288
#define DIM   128
#define BI    32
#define BJ    64
#define EPSF  1e-7f
#define MAXN  (1.0f - 1e-3f)
#define NEG_SLOPE 0.2f

// Scratch (device globals — no allocation allowed)
__device__ float g_xt[N_PTS * DIM];   // logmap0(x), pre-rounded to tf32
__device__ float g_wh1[N_PTS];
__device__ float g_wh2[N_PTS];

__device__ __forceinline__ unsigned f2tf32(float f) {
    unsigned u;
    asm("cvt.rna.tf32.f32 %0, %1;" : "=r"(u) : "f"(f));
    return u;
}

// m16n8k8 tf32 MMA, fp32 accumulate (canonical fragment layouts)
#define MMA_TF32(d, a0, a1, a2, a3, b0, b1)                                   \
    asm volatile(                                                             \
        "mma.sync.aligned.m16n8k8.row.col.f32.tf32.tf32.f32 "                 \
        "{%0,%1,%2,%3}, {%4,%5,%6,%7}, {%8,%9}, {%0,%1,%2,%3};"               \
        : "+f"(d[0]), "+f"(d[1]), "+f"(d[2]), "+f"(d[3])                      \
        : "r"(a0), "r"(a1), "r"(a2), "r"(a3), "r"(b0), "r"(b1))

// ---------------------------------------------------------------------------
// Kernel 1: per-row logmap0 (full fp32) + wh1/wh2 projections; store xt as tf32
// ---------------------------------------------------------------------------
__global__ void prep_kernel(const float* __restrict__ x, const float* __restrict__ a) {
    int i = blockIdx.x;
    int d = threadIdx.x;
    float xv = x[(size_t)i * DIM + d];
    float s0 = xv * xv;
    float s1 = xv * a[d];
    float s2 = xv * a[DIM + d];
#pragma unroll
    for (int o = 16; o > 0; o >>= 1) {
        s0 += __shfl_down_sync(0xffffffffu, s0, o);
        s1 += __shfl_down_sync(0xffffffffu, s1, o);
        s2 += __shfl_down_sync(0xffffffffu, s2, o);
    }
    __shared__ float sm0[4], sm1[4], sm2[4];
    __shared__ float sscale;
    int w = d >> 5, l = d & 31;
    if (l == 0) { sm0[w] = s0; sm1[w] = s1; sm2[w] = s2; }
    __syncthreads();
    if (d == 0) {
        float t0 = sm0[0] + sm0[1] + sm0[2] + sm0[3];
        float t1 = sm1[0] + sm1[1] + sm1[2] + sm1[3];
        float t2 = sm2[0] + sm2[1] + sm2[2] + sm2[3];
        float n  = sqrtf(t0);
        float nc = fminf(fmaxf(n, EPSF), 1.0f - EPSF);
        float sc = atanhf(nc) / nc;
        sscale   = sc;
        g_wh1[i] = sc * t1;
        g_wh2[i] = sc * t2;
    }
    __syncthreads();
    g_xt[(size_t)i * DIM + d] = __uint_as_float(f2tf32(xv * sscale));
}

// ---------------------------------------------------------------------------
// Kernel 2: fused masked-softmax attention; P@xt via tf32 mma.sync (HMMA).
// 256 threads = 8 warps. Warp w: m-tile (w&1)*16, col-slice (w>>1)*32.
// j-permutation L(8s+tig+4t) = 8s+2tig+t applied to P cols AND xt rows so
// A frags load as LDS.64 pairs and B frags as LDS.128 (conflict-free).
// ---------------------------------------------------------------------------
__global__ __launch_bounds__(256, 3) void attn_kernel(const int* __restrict__ adj,
                                                      float* __restrict__ out) {
    __shared__ __align__(16) float xt_s[BJ][132];  // 33.8 KB, j-permuted rows, tf32
    __shared__ __align__(16) float pT[BI][72];     // 9.2 KB, j-permuted cols, tf32
    __shared__ float m_s[BI], l_s[BI], r_s[BI];

    const int tid  = threadIdx.x;
    const int i0   = blockIdx.x * BI;
    const int lane = tid & 31, w = tid >> 5;
    const int g    = lane >> 2, tig = lane & 3;     // groupID / thread-in-group
    const int m0   = (w & 1) << 4;                  // warp m-tile base row
    const int sl   = (w >> 1) << 5;                 // warp col-slice base
    const int colb = sl + (g << 2);                 // B-frag float4 base col

    const int p_row = tid >> 3, p_jo = tid & 7;
    const int lbase = ((p_jo & 3) << 1) + (p_jo >> 2);  // L() of p_jo

    float acc[4][4];  // [nt][c0,c1,c2,c3]
#pragma unroll
    for (int nt = 0; nt < 4; nt++)
#pragma unroll
        for (int c = 0; c < 4; c++) acc[nt][c] = 0.f;

    if (tid < BI) { m_s[tid] = -INFINITY; l_s[tid] = 0.f; }

    const float wh1 = g_wh1[i0 + p_row];
    const int* adjrow = adj + (size_t)(i0 + p_row) * N_PTS;

    __syncthreads();

    for (int j0 = 0; j0 < N_PTS; j0 += BJ) {
        // ---- load xt tile (L2), rows permuted by L ----
#pragma unroll
        for (int s = 0; s < 8; s++) {
            int slot = tid + (s << 8);
            int jn = slot >> 5;
            int c4 = (slot & 31) << 2;
            int r7 = jn & 7;
            int lr = (jn & ~7) + ((r7 & 3) << 1) + (r7 >> 2);
            *(float4*)&xt_s[lr][c4] =
                *(const float4*)&g_xt[(size_t)(j0 + jn) * DIM + c4];
        }

        // ---- phase 1: scores + online max ----
        float e[8];
        float tmax = -INFINITY;
#pragma unroll
        for (int k = 0; k < 8; k++) {
            int j = j0 + p_jo + (k << 3);
            float tv = wh1 + g_wh2[j];
            float sc = tv >= 0.f ? tv : NEG_SLOPE * tv;
            e[k] = (adjrow[j] > 0) ? sc : -INFINITY;
            tmax = fmaxf(tmax, e[k]);
        }
        tmax = fmaxf(tmax, __shfl_xor_sync(0xffffffffu, tmax, 1));
        tmax = fmaxf(tmax, __shfl_xor_sync(0xffffffffu, tmax, 2));
        tmax = fmaxf(tmax, __shfl_xor_sync(0xffffffffu, tmax, 4));
        if (p_jo == 0) {
            float mo = m_s[p_row];
            float mn = fmaxf(mo, tmax);
            r_s[p_row] = (mn == -INFINITY) ? 1.f
                       : ((mo == -INFINITY) ? 0.f : __expf(mo - mn));
            m_s[p_row] = mn;
        }
        __syncthreads();

        // ---- p = exp(e-m) -> tf32, stored j-permuted; update l ----
        float mn = m_s[p_row];
        float lsum = 0.f;
#pragma unroll
        for (int k = 0; k < 8; k++) {
            float p  = (mn == -INFINITY) ? 0.f : __expf(e[k] - mn);
            float pt = __uint_as_float(f2tf32(p));   // sum post-rounding for consistency
            pT[p_row][(k << 3) + lbase] = pt;
            lsum += pt;
        }
        lsum += __shfl_xor_sync(0xffffffffu, lsum, 1);
        lsum += __shfl_xor_sync(0xffffffffu, lsum, 2);
        lsum += __shfl_xor_sync(0xffffffffu, lsum, 4);
        if (p_jo == 0) l_s[p_row] = l_s[p_row] * r_s[p_row] + lsum;

        // ---- rescale accumulators (rows m0+g and m0+8+g) ----
        float r0 = r_s[m0 + g], r1 = r_s[m0 + 8 + g];
#pragma unroll
        for (int nt = 0; nt < 4; nt++) {
            acc[nt][0] *= r0; acc[nt][1] *= r0;
            acc[nt][2] *= r1; acc[nt][3] *= r1;
        }
        __syncthreads();

        // ---- phase 2: 32 tf32 MMAs per warp ----
#pragma unroll
        for (int s = 0; s < 8; s++) {
            int lr = (s << 3) + (tig << 1);
            float2 pa0 = *(const float2*)&pT[m0 + g][lr];       // j=8s+tig, 8s+tig+4
            float2 pa1 = *(const float2*)&pT[m0 + 8 + g][lr];
            uint4  xb0 = *(const uint4*)&xt_s[lr][colb];        // j=8s+tig row
            uint4  xb1 = *(const uint4*)&xt_s[lr + 1][colb];    // j=8s+tig+4 row
            unsigned a0 = __float_as_uint(pa0.x), a1 = __float_as_uint(pa1.x);
            unsigned a2 = __float_as_uint(pa0.y), a3 = __float_as_uint(pa1.y);
            MMA_TF32(acc[0], a0, a1, a2, a3, xb0.x, xb1.x);
            MMA_TF32(acc[1], a0, a1, a2, a3, xb0.y, xb1.y);
            MMA_TF32(acc[2], a0, a1, a2, a3, xb0.z, xb1.z);
            MMA_TF32(acc[3], a0, a1, a2, a3, xb0.w, xb1.w);
        }
        __syncthreads();
    }

    // ---- scatter accumulators into smem (unpermuted cols), reuse xt_s ----
    // logical bcol b -> actual col 4b + nt;  c0/c1 at b = 2tig, 2tig+1
#pragma unroll
    for (int nt = 0; nt < 4; nt++) {
        xt_s[m0 + g][sl + (tig << 3) + nt]         = acc[nt][0];
        xt_s[m0 + g][sl + (tig << 3) + 4 + nt]     = acc[nt][1];
        xt_s[m0 + 8 + g][sl + (tig << 3) + nt]     = acc[nt][2];
        xt_s[m0 + 8 + g][sl + (tig << 3) + 4 + nt] = acc[nt][3];
    }
    __syncthreads();

    // ---- epilogue: v = acc/l; expmap0; proj ----
    {
        int cx = lane;  // dims 4cx..4cx+3
#pragma unroll
        for (int r = 0; r < 4; r++) {
            int row = (w << 2) + r;
            float linv = 1.f / l_s[row];
            float4 v = *(const float4*)&xt_s[row][cx << 2];
            float v0 = v.x * linv, v1 = v.y * linv;
            float v2 = v.z * linv, v3 = v.w * linv;
            float part = v0 * v0 + v1 * v1 + v2 * v2 + v3 * v3;
#pragma unroll
            for (int o2 = 16; o2 > 0; o2 >>= 1)
                part += __shfl_xor_sync(0xffffffffu, part, o2);
            float n  = sqrtf(part);
            float nc = fmaxf(n, EPSF);
            float sc = tanhf(nc) / nc;            // expmap0 scale
            float ny = fmaxf(sc * n, EPSF);       // ||y||
            float f  = (ny > MAXN) ? sc * (MAXN / ny) : sc;  // proj
            *(float4*)&out[(size_t)(i0 + row) * DIM + (cx << 2)] =
                make_float4(v0 * f, v1 * f, v2 * f, v3 * f);
        }
    }
}

// ---------------------------------------------------------------------------
extern "C" void kernel_launch(void* const* d_in, const int* in_sizes, int n_in,
                              void* d_out, int out_size) {
    const float* x = nullptr;
    const int*   adj = nullptr;
    const float* a = nullptr;
    for (int i = 0; i < n_in; i++) {
        if (in_sizes[i] == N_PTS * DIM)      x   = (const float*)d_in[i];
        else if (in_sizes[i] == 2 * DIM)     a   = (const float*)d_in[i];
        else                                 adj = (const int*)d_in[i];
    }
    float* out = (float*)d_out;

    prep_kernel<<<N_PTS, DIM>>>(x, a);
    attn_kernel<<<N_PTS / BI, 256>>>(adj, out);
}

// round 11
// speedup vs baseline: 1.1019x; 1.1019x over previous
#include <cuda_runtime.h>
#include <math.h>

#define N_PTS 12288
#define DIM   128
#define BI    32
#define BJ    48
#define TILES (N_PTS / BJ)   /* 256 */
#define EPSF  1e-7f
#define MAXN  (1.0f - 1e-3f)

// Scratch (device globals — no allocation allowed)
__device__ float  g_xt[N_PTS * DIM];   // logmap0(x), pre-rounded to tf32
__device__ float4 g_rw[N_PTS];         // per-row:  (E1=e^wh1, F1=e^{0.2wh1}, Ethr=e^{-wh1}, 0)
__device__ float2 g_ef[N_PTS];         // per-col:  (e2=e^wh2, f2=e^{0.2wh2})

__device__ __forceinline__ unsigned f2tf32(float f) {
    unsigned u;
    asm("cvt.rna.tf32.f32 %0, %1;" : "=r"(u) : "f"(f));
    return u;
}

// m16n8k8 tf32 MMA, fp32 accumulate
#define MMA_TF32(d, a0, a1, a2, a3, b0, b1)                                   \
    asm volatile(                                                             \
        "mma.sync.aligned.m16n8k8.row.col.f32.tf32.tf32.f32 "                 \
        "{%0,%1,%2,%3}, {%4,%5,%6,%7}, {%8,%9}, {%0,%1,%2,%3};"               \
        : "+f"(d[0]), "+f"(d[1]), "+f"(d[2]), "+f"(d[3])                      \
        : "r"(a0), "r"(a1), "r"(a2), "r"(a3), "r"(b0), "r"(b1))

// ---------------------------------------------------------------------------
// Kernel 1: logmap0 + wh projections; factor exp terms; store xt as tf32
// ---------------------------------------------------------------------------
__global__ void prep_kernel(const float* __restrict__ x, const float* __restrict__ a) {
    int i = blockIdx.x;
    int d = threadIdx.x;
    float xv = x[(size_t)i * DIM + d];
    float s0 = xv * xv;
    float s1 = xv * a[d];
    float s2 = xv * a[DIM + d];
#pragma unroll
    for (int o = 16; o > 0; o >>= 1) {
        s0 += __shfl_down_sync(0xffffffffu, s0, o);
        s1 += __shfl_down_sync(0xffffffffu, s1, o);
        s2 += __shfl_down_sync(0xffffffffu, s2, o);
    }
    __shared__ float sm0[4], sm1[4], sm2[4];
    __shared__ float sscale;
    int w = d >> 5, l = d & 31;
    if (l == 0) { sm0[w] = s0; sm1[w] = s1; sm2[w] = s2; }
    __syncthreads();
    if (d == 0) {
        float t0 = sm0[0] + sm0[1] + sm0[2] + sm0[3];
        float t1 = sm1[0] + sm1[1] + sm1[2] + sm1[3];
        float t2 = sm2[0] + sm2[1] + sm2[2] + sm2[3];
        float n  = sqrtf(t0);
        float nc = fminf(fmaxf(n, EPSF), 1.0f - EPSF);
        float sc = atanhf(nc) / nc;
        sscale   = sc;
        float wh1 = sc * t1, wh2 = sc * t2;
        g_rw[i] = make_float4(expf(wh1), expf(0.2f * wh1), expf(-wh1), 0.f);
        g_ef[i] = make_float2(expf(wh2), expf(0.2f * wh2));
    }
    __syncthreads();
    g_xt[(size_t)i * DIM + d] = __uint_as_float(f2tf32(xv * sscale));
}

// ---------------------------------------------------------------------------
// Kernel 2: fused masked attention, no-max softmax, pipelined (1 sync/tile).
// 256 threads = 8 warps. Warp w: m-tile (w&1)*16, col-slice (w>>1)*32.
// j-permutation L(8s+tig+4t)=8s+2tig+t on P cols AND xt rows (as R10).
// ---------------------------------------------------------------------------
__global__ __launch_bounds__(256, 3) void attn_kernel(const int* __restrict__ adj,
                                                      float* __restrict__ out) {
    __shared__ __align__(16) float xt_s[2][BJ][132];  // 50.7 KB, tf32, j-permuted rows
    __shared__ __align__(16) float pTs[2][BI][56];    // 14.3 KB, tf32, j-permuted cols
    __shared__ float l_s[BI];

    const int tid  = threadIdx.x;
    const int i0   = blockIdx.x * BI;
    const int lane = tid & 31, w = tid >> 5;
    const int g    = lane >> 2, tig = lane & 3;
    const int m0   = (w & 1) << 4;
    const int sl   = (w >> 1) << 5;
    const int colb = sl + (g << 2);
    const int p_row = tid >> 3, p_jo = tid & 7;
    const int lbase = ((p_jo & 3) << 1) + (p_jo >> 2);

    float acc[4][4];
#pragma unroll
    for (int nt = 0; nt < 4; nt++)
#pragma unroll
        for (int c = 0; c < 4; c++) acc[nt][c] = 0.f;

    // cp.async address precompute (6 x 16B chunks per thread per tile)
    unsigned xtb[2];
    xtb[0] = (unsigned)__cvta_generic_to_shared(&xt_s[0][0][0]);
    xtb[1] = (unsigned)__cvta_generic_to_shared(&xt_s[1][0][0]);
    unsigned doff[6];
    int      soff[6];
#pragma unroll
    for (int s = 0; s < 6; s++) {
        int slot = tid + (s << 8);
        int jn = slot >> 5;
        int c4 = (slot & 31) << 2;
        int r7 = jn & 7;
        int lr = (jn & ~7) + ((r7 & 3) << 1) + (r7 >> 2);
        doff[s] = (unsigned)((lr * 132 + c4) << 2);
        soff[s] = jn * DIM + c4;
    }

    // phase-1 operand bases
    const float4 rw = g_rw[i0 + p_row];
    const float E1 = rw.x, F1 = rw.y, Ethr = rw.z;
    const int*    adjr = adj + (size_t)(i0 + p_row) * N_PTS + p_jo;
    const float2* efr  = g_ef + p_jo;

    // prologue: start xt tile 0 copy; prefetch tile-0 adj/ef operands
    {
        const float* srcb = g_xt;
#pragma unroll
        for (int s = 0; s < 6; s++)
            asm volatile("cp.async.cg.shared.global [%0], [%1], 16;"
                         :: "r"(xtb[0] + doff[s]), "l"(srcb + soff[s]));
        asm volatile("cp.async.commit_group;");
    }
    int    mv[6];
    float2 ef[6];
#pragma unroll
    for (int k = 0; k < 6; k++) { mv[k] = adjr[k << 3]; ef[k] = efr[k << 3]; }

    float lsum = 0.f;

    for (int t = 0; t < TILES; t++) {
        const int b = t & 1;

        // ---- compute p for tile t from prefetched regs; store tf32 ----
        float* ps = &pTs[b][p_row][lbase];
#pragma unroll
        for (int k = 0; k < 6; k++) {
            float pe = (ef[k].x >= Ethr) ? (E1 * ef[k].x) : (F1 * ef[k].y);
            float p  = (mv[k] > 0) ? pe : 0.f;
            float pt = __uint_as_float(f2tf32(p));
            ps[k << 3] = pt;
            lsum += pt;
        }

        asm volatile("cp.async.wait_group 0;" ::: "memory");
        __syncthreads();

        // ---- launch tile t+1: xt copy + operand prefetch (hidden by mma) ----
        if (t + 1 < TILES) {
            const float* srcb = g_xt + (size_t)(t + 1) * BJ * DIM;
            unsigned base = xtb[b ^ 1];
#pragma unroll
            for (int s = 0; s < 6; s++)
                asm volatile("cp.async.cg.shared.global [%0], [%1], 16;"
                             :: "r"(base + doff[s]), "l"(srcb + soff[s]));
            asm volatile("cp.async.commit_group;");
            const int*    at = adjr + (t + 1) * BJ;
            const float2* et = efr + (t + 1) * BJ;
#pragma unroll
            for (int k = 0; k < 6; k++) { mv[k] = at[k << 3]; ef[k] = et[k << 3]; }
        }

        // ---- mma over tile t ----
        const float (*xs)[132] = xt_s[b];
        const float (*pp)[56]  = pTs[b];
#pragma unroll
        for (int s = 0; s < 6; s++) {
            int lr = (s << 3) + (tig << 1);
            float2 pa0 = *(const float2*)&pp[m0 + g][lr];
            float2 pa1 = *(const float2*)&pp[m0 + 8 + g][lr];
            uint4  xb0 = *(const uint4*)&xs[lr][colb];
            uint4  xb1 = *(const uint4*)&xs[lr + 1][colb];
            unsigned a0 = __float_as_uint(pa0.x), a1 = __float_as_uint(pa1.x);
            unsigned a2 = __float_as_uint(pa0.y), a3 = __float_as_uint(pa1.y);
            MMA_TF32(acc[0], a0, a1, a2, a3, xb0.x, xb1.x);
            MMA_TF32(acc[1], a0, a1, a2, a3, xb0.y, xb1.y);
            MMA_TF32(acc[2], a0, a1, a2, a3, xb0.z, xb1.z);
            MMA_TF32(acc[3], a0, a1, a2, a3, xb0.w, xb1.w);
        }
    }

    // ---- finalize l: reduce over the 8 p_jo lanes sharing each row ----
    lsum += __shfl_xor_sync(0xffffffffu, lsum, 1);
    lsum += __shfl_xor_sync(0xffffffffu, lsum, 2);
    lsum += __shfl_xor_sync(0xffffffffu, lsum, 4);
    if ((lane & 7) == 0) l_s[p_row] = lsum;

    // ---- scatter accumulators into xt_s[0] (unpermuted cols) ----
#pragma unroll
    for (int nt = 0; nt < 4; nt++) {
        xt_s[0][m0 + g][sl + (tig << 3) + nt]         = acc[nt][0];
        xt_s[0][m0 + g][sl + (tig << 3) + 4 + nt]     = acc[nt][1];
        xt_s[0][m0 + 8 + g][sl + (tig << 3) + nt]     = acc[nt][2];
        xt_s[0][m0 + 8 + g][sl + (tig << 3) + 4 + nt] = acc[nt][3];
    }
    __syncthreads();

    // ---- epilogue: v = acc/l; expmap0; proj ----
    {
        int cx = lane;  // dims 4cx..4cx+3
#pragma unroll
        for (int r = 0; r < 4; r++) {
            int row = (w << 2) + r;
            float linv = 1.f / l_s[row];
            float4 v = *(const float4*)&xt_s[0][row][cx << 2];
            float v0 = v.x * linv, v1 = v.y * linv;
            float v2 = v.z * linv, v3 = v.w * linv;
            float part = v0 * v0 + v1 * v1 + v2 * v2 + v3 * v3;
#pragma unroll
            for (int o2 = 16; o2 > 0; o2 >>= 1)
                part += __shfl_xor_sync(0xffffffffu, part, o2);
            float n  = sqrtf(part);
            float nc = fmaxf(n, EPSF);
            float sc = tanhf(nc) / nc;            // expmap0 scale
            float ny = fmaxf(sc * n, EPSF);       // ||y||
            float f  = (ny > MAXN) ? sc * (MAXN / ny) : sc;  // proj
            *(float4*)&out[(size_t)(i0 + row) * DIM + (cx << 2)] =
                make_float4(v0 * f, v1 * f, v2 * f, v3 * f);
        }
    }
}

// ---------------------------------------------------------------------------
extern "C" void kernel_launch(void* const* d_in, const int* in_sizes, int n_in,
                              void* d_out, int out_size) {
    const float* x = nullptr;
    const int*   adj = nullptr;
    const float* a = nullptr;
    for (int i = 0; i < n_in; i++) {
        if (in_sizes[i] == N_PTS * DIM)      x   = (const float*)d_in[i];
        else if (in_sizes[i] == 2 * DIM)     a   = (const float*)d_in[i];
        else                                 adj = (const int*)d_in[i];
    }
    float* out = (float*)d_out;

    prep_kernel<<<N_PTS, DIM>>>(x, a);
    attn_kernel<<<N_PTS / BI, 256>>>(adj, out);
}